// round 1
// baseline (speedup 1.0000x reference)
#include <cuda_runtime.h>
#include <math.h>

#define NN   100000
#define NE   1600000
#define ET   (NE + NN)
#define VISD 512
#define TXTD 768
#define FEATD 131
#define LDA  132          // padded row stride for 131-wide features (528B, 16B-aligned)
#define HID  128

// ---------------- scratch (device globals; no allocation allowed) ----------------
static __device__ float    g_inp [NN * LDA];   // projected input features [N,131]
static __device__ float    g_node[NN * LDA];   // scattered + gelu'd node features
static __device__ float    g_h   [NN * HID];   // per-layer transformed features h = x @ W
static __device__ float    g_x1  [NN * HID];   // relu(layer0 output)
static __device__ float    g_agg [NN * HID];   // per-layer aggregation accumulator
static __device__ float    g_as  [NN];
static __device__ float    g_ad  [NN];
static __device__ unsigned g_emax[NN];         // ordered-encoded float max
static __device__ float    g_den [NN];
static __device__ float    g_e   [ET];         // per-edge e, then exp(e - max)
static __device__ float    g_ang [NN * 2];
static __device__ float    g_dis [NN * 2];

// ---------------- helpers ----------------
__device__ __forceinline__ float gelu_exact(float x) {
    return 0.5f * x * (1.0f + erff(x * 0.70710678118654752f));
}
__device__ __forceinline__ unsigned f2o(float f) {          // monotonic float->uint
    unsigned u = __float_as_uint(f);
    return (u & 0x80000000u) ? ~u : (u | 0x80000000u);
}
__device__ __forceinline__ float o2f(unsigned u) {
    return (u & 0x80000000u) ? __uint_as_float(u & 0x7fffffffu) : __uint_as_float(~u);
}

__global__ void fill_f(float* p, float v, int n) {
    int i = blockIdx.x * blockDim.x + threadIdx.x;
    if (i < n) p[i] = v;
}
__global__ void fill_u(unsigned* p, unsigned v, int n) {
    int i = blockIdx.x * blockDim.x + threadIdx.x;
    if (i < n) p[i] = v;
}

// ---------------- generic tiled fp32 GEMM: C[r, ccol0+col0+j] = A[r,:K] @ W[:, col0+j] (+bias) ----------------
// A: [M,K] with row stride lda; W: [K, wcols] row-major; block tile 64x64, BK=16, 256 threads.
__global__ void gemm_tile(const float* __restrict__ A, int lda, int K, int M,
                          const float* __restrict__ W, int wcols,
                          const float* __restrict__ bias,
                          float* __restrict__ C, int ldc, int ccol0)
{
    __shared__ float As[16][64];
    __shared__ float Bs[16][64 + 4];
    const int row0 = blockIdx.x * 64;
    const int col0 = blockIdx.y * 64;          // within W's columns
    const int t  = threadIdx.x;                // 256 threads
    const int tx = t & 15, ty = t >> 4;
    float acc[4][4] = {};

    for (int k0 = 0; k0 < K; k0 += 16) {
        // load A chunk: 64 rows x 16 k, one float4 per thread
        {
            int r  = t >> 2;
            int kk = (t & 3) * 4;
            int gr = row0 + r;
            float4 v = make_float4(0.f, 0.f, 0.f, 0.f);
            if (gr < M) {
                if (k0 + kk + 3 < K) {
                    v = *reinterpret_cast<const float4*>(&A[(size_t)gr * lda + k0 + kk]);
                } else {
                    float tmp[4] = {0.f, 0.f, 0.f, 0.f};
                    #pragma unroll
                    for (int c = 0; c < 4; c++) {
                        int k = k0 + kk + c;
                        if (k < K) tmp[c] = A[(size_t)gr * lda + k];
                    }
                    v = make_float4(tmp[0], tmp[1], tmp[2], tmp[3]);
                }
            }
            As[kk + 0][r] = v.x; As[kk + 1][r] = v.y;
            As[kk + 2][r] = v.z; As[kk + 3][r] = v.w;
        }
        // load W chunk: 16 k x 64 cols
        #pragma unroll
        for (int i = 0; i < 4; i++) {
            int idx = t + 256 * i;
            int kr = idx >> 6, c = idx & 63;
            int k = k0 + kr;
            Bs[kr][c] = (k < K) ? W[(size_t)k * wcols + col0 + c] : 0.f;
        }
        __syncthreads();
        #pragma unroll
        for (int k = 0; k < 16; k++) {
            float a[4], b[4];
            #pragma unroll
            for (int i = 0; i < 4; i++) a[i] = As[k][ty * 4 + i];
            #pragma unroll
            for (int j = 0; j < 4; j++) b[j] = Bs[k][tx * 4 + j];
            #pragma unroll
            for (int i = 0; i < 4; i++)
                #pragma unroll
                for (int j = 0; j < 4; j++)
                    acc[i][j] = fmaf(a[i], b[j], acc[i][j]);
        }
        __syncthreads();
    }
    #pragma unroll
    for (int i = 0; i < 4; i++) {
        int r = row0 + ty * 4 + i;
        if (r >= M) continue;
        #pragma unroll
        for (int j = 0; j < 4; j++) {
            int c = col0 + tx * 4 + j;
            float v = acc[i][j];
            if (bias) v += bias[c];
            C[(size_t)r * ldc + ccol0 + c] = v;
        }
    }
}

// ---------------- copy aspect ratios into inp cols 128..130 ----------------
__global__ void ars_copy(const float* __restrict__ ars) {
    int i = blockIdx.x * blockDim.x + threadIdx.x;
    if (i >= NN) return;
    g_inp[(size_t)i * LDA + 128] = ars[3 * i + 0];
    g_inp[(size_t)i * LDA + 129] = ars[3 * i + 1];
    g_inp[(size_t)i * LDA + 130] = ars[3 * i + 2];
}

// ---------------- scatter inp rows to node[content_indices] with exact GELU ----------------
__global__ void scatter_gelu(const int* __restrict__ ci) {
    int row = blockIdx.x;
    int dst = ci[row];
    for (int f = threadIdx.x; f < FEATD; f += blockDim.x) {
        float v = g_inp[(size_t)row * LDA + f];
        g_node[(size_t)dst * LDA + f] = gelu_exact(v);
    }
}

// ---------------- per-node attention scores: a_s = h . att_src, a_d = h . att_dst ----------------
__global__ void attn_scores(const float* __restrict__ ws, const float* __restrict__ wd) {
    int gw   = (blockIdx.x * blockDim.x + threadIdx.x) >> 5;
    int lane = threadIdx.x & 31;
    if (gw >= NN) return;
    float4 hv = *reinterpret_cast<const float4*>(&g_h[(size_t)gw * HID + lane * 4]);
    float4 a  = *reinterpret_cast<const float4*>(&ws[lane * 4]);
    float4 b  = *reinterpret_cast<const float4*>(&wd[lane * 4]);
    float s = hv.x * a.x + hv.y * a.y + hv.z * a.z + hv.w * a.w;
    float d = hv.x * b.x + hv.y * b.y + hv.z * b.z + hv.w * b.w;
    #pragma unroll
    for (int o = 16; o; o >>= 1) {
        s += __shfl_xor_sync(0xffffffffu, s, o);
        d += __shfl_xor_sync(0xffffffffu, d, o);
    }
    if (lane == 0) { g_as[gw] = s; g_ad[gw] = d; }
}

// ---------------- edge pass 1: e = leaky_relu(a_s[s]+a_d[d]); segment max ----------------
__global__ void edge_pass1(const int* __restrict__ edges) {
    int i = blockIdx.x * blockDim.x + threadIdx.x;
    if (i >= ET) return;
    int s, d;
    if (i < NE) { s = edges[2 * i]; d = edges[2 * i + 1]; }
    else        { s = d = i - NE; }
    float e = g_as[s] + g_ad[d];
    e = (e > 0.f) ? e : 0.2f * e;
    g_e[i] = e;
    atomicMax(&g_emax[d], f2o(e));
}

// ---------------- edge pass 2: ee = exp(e - max[d]); segment sum ----------------
__global__ void edge_pass2(const int* __restrict__ edges) {
    int i = blockIdx.x * blockDim.x + threadIdx.x;
    if (i >= ET) return;
    int d;
    if (i < NE) d = edges[2 * i + 1];
    else        d = i - NE;
    float ee = expf(g_e[i] - o2f(g_emax[d]));
    g_e[i] = ee;
    atomicAdd(&g_den[d], ee);
}

// ---------------- edge pass 3: agg[d] += alpha * h[s]  (warp per edge) ----------------
__global__ void edge_pass3(const int* __restrict__ edges) {
    int w    = (blockIdx.x * blockDim.x + threadIdx.x) >> 5;
    int lane = threadIdx.x & 31;
    if (w >= ET) return;
    int s, d;
    if (w < NE) { s = edges[2 * w]; d = edges[2 * w + 1]; }
    else        { s = d = w - NE; }
    float alpha = g_e[w] / (g_den[d] + 1e-16f);
    float4 hv = *reinterpret_cast<const float4*>(&g_h[(size_t)s * HID + lane * 4]);
    float* dst = &g_agg[(size_t)d * HID + lane * 4];
    atomicAdd(dst + 0, hv.x * alpha);
    atomicAdd(dst + 1, hv.y * alpha);
    atomicAdd(dst + 2, hv.z * alpha);
    atomicAdd(dst + 3, hv.w * alpha);
}

// ---------------- bias + relu ----------------
__global__ void bias_relu(const float* __restrict__ b) {
    int i = blockIdx.x * blockDim.x + threadIdx.x;
    if (i >= NN * HID) return;
    float v = g_agg[i] + b[i & (HID - 1)];
    g_x1[i] = (v > 0.f) ? v : 0.f;
}

// ---------------- final per-node: out = gelu(agg + b1); angles/dists heads ----------------
__global__ void final_node(const float* __restrict__ b1,
                           const float* __restrict__ Wa, const float* __restrict__ ba,
                           const float* __restrict__ Wd, const float* __restrict__ bd,
                           float* __restrict__ out)
{
    int gw   = (blockIdx.x * blockDim.x + threadIdx.x) >> 5;
    int lane = threadIdx.x & 31;
    if (gw >= NN) return;
    float a0 = 0.f, a1 = 0.f, d0 = 0.f, d1 = 0.f;
    float4 g;
    {
        float4 v = *reinterpret_cast<const float4*>(&g_agg[(size_t)gw * HID + lane * 4]);
        float4 bb = *reinterpret_cast<const float4*>(&b1[lane * 4]);
        g.x = gelu_exact(v.x + bb.x);
        g.y = gelu_exact(v.y + bb.y);
        g.z = gelu_exact(v.z + bb.z);
        g.w = gelu_exact(v.w + bb.w);
    }
    *reinterpret_cast<float4*>(&out[(size_t)gw * HID + lane * 4]) = g;
    int k = lane * 4;
    a0 = g.x * Wa[2 * k] + g.y * Wa[2 * (k + 1)] + g.z * Wa[2 * (k + 2)] + g.w * Wa[2 * (k + 3)];
    a1 = g.x * Wa[2 * k + 1] + g.y * Wa[2 * (k + 1) + 1] + g.z * Wa[2 * (k + 2) + 1] + g.w * Wa[2 * (k + 3) + 1];
    d0 = g.x * Wd[2 * k] + g.y * Wd[2 * (k + 1)] + g.z * Wd[2 * (k + 2)] + g.w * Wd[2 * (k + 3)];
    d1 = g.x * Wd[2 * k + 1] + g.y * Wd[2 * (k + 1) + 1] + g.z * Wd[2 * (k + 2) + 1] + g.w * Wd[2 * (k + 3) + 1];
    #pragma unroll
    for (int o = 16; o; o >>= 1) {
        a0 += __shfl_xor_sync(0xffffffffu, a0, o);
        a1 += __shfl_xor_sync(0xffffffffu, a1, o);
        d0 += __shfl_xor_sync(0xffffffffu, d0, o);
        d1 += __shfl_xor_sync(0xffffffffu, d1, o);
    }
    if (lane == 0) {
        g_ang[2 * gw]     = a0 + ba[0];
        g_ang[2 * gw + 1] = a1 + ba[1];
        g_dis[2 * gw]     = d0 + bd[0];
        g_dis[2 * gw + 1] = d1 + bd[1];
    }
}

// ---------------- edge prediction: dot of head outputs over original edges ----------------
__global__ void pred_kernel(const int* __restrict__ edges, float* __restrict__ pred) {
    int i = blockIdx.x * blockDim.x + threadIdx.x;
    if (i >= NE) return;
    int s = edges[2 * i], d = edges[2 * i + 1];
    float ap = g_ang[2 * s] * g_ang[2 * d] + g_ang[2 * s + 1] * g_ang[2 * d + 1];
    float dp = g_dis[2 * s] * g_dis[2 * d] + g_dis[2 * s + 1] * g_dis[2 * d + 1];
    pred[2 * i]     = ap;
    pred[2 * i + 1] = dp;
}

// ---------------- launch ----------------
extern "C" void kernel_launch(void* const* d_in, const int* in_sizes, int n_in,
                              void* d_out, int out_size)
{
    const float* img  = (const float*)d_in[0];
    const float* txt  = (const float*)d_in[1];
    const int*   ci   = (const int*)  d_in[2];
    const int*   edges= (const int*)  d_in[4];
    const float* ars  = (const float*)d_in[5];
    const float* Wi   = (const float*)d_in[6];
    const float* bi   = (const float*)d_in[7];
    const float* Wt   = (const float*)d_in[8];
    const float* bt   = (const float*)d_in[9];
    const float* W0   = (const float*)d_in[10];
    const float* as0  = (const float*)d_in[11];
    const float* ad0  = (const float*)d_in[12];
    const float* b0   = (const float*)d_in[13];
    const float* W1   = (const float*)d_in[14];
    const float* as1  = (const float*)d_in[15];
    const float* ad1  = (const float*)d_in[16];
    const float* b1   = (const float*)d_in[17];
    const float* Wa   = (const float*)d_in[18];
    const float* ba   = (const float*)d_in[19];
    const float* Wd   = (const float*)d_in[20];
    const float* bd   = (const float*)d_in[21];
    float* out  = (float*)d_out;                       // [N,128]
    float* pred = (float*)d_out + (size_t)NN * HID;    // [E,2]

    float *p_inp, *p_node, *p_h, *p_x1, *p_agg, *p_den;
    unsigned* p_emax;
    cudaGetSymbolAddress((void**)&p_inp,  g_inp);
    cudaGetSymbolAddress((void**)&p_node, g_node);
    cudaGetSymbolAddress((void**)&p_h,    g_h);
    cudaGetSymbolAddress((void**)&p_x1,   g_x1);
    cudaGetSymbolAddress((void**)&p_agg,  g_agg);
    cudaGetSymbolAddress((void**)&p_den,  g_den);
    cudaGetSymbolAddress((void**)&p_emax, g_emax);

    const int T = 256;
    const int gemm_gx = (NN + 63) / 64;

    // 0) zero node buffer (scatter target)
    fill_f<<<(NN * LDA + T - 1) / T, T>>>(p_node, 0.f, NN * LDA);

    // 1) input projections into g_inp
    gemm_tile<<<dim3(gemm_gx, 1), T>>>(img, VISD, VISD, NN, Wi, 64, bi, p_inp, LDA, 0);
    gemm_tile<<<dim3(gemm_gx, 1), T>>>(txt, TXTD, TXTD, NN, Wt, 64, bt, p_inp, LDA, 64);
    ars_copy<<<(NN + T - 1) / T, T>>>(ars);

    // 2) scatter + gelu -> node features
    scatter_gelu<<<NN, 128>>>(ci);

    const int edge_blocks  = (ET + T - 1) / T;
    const int edge_wblocks = ((ET * 32) + T - 1) / T;
    const int node_wblocks = ((NN * 32) + T - 1) / T;

    // ===== GAT layer 0 =====
    gemm_tile<<<dim3(gemm_gx, 2), T>>>(p_node, LDA, FEATD, NN, W0, HID, nullptr, p_h, HID, 0);
    attn_scores<<<node_wblocks, T>>>(as0, ad0);
    fill_u<<<(NN + T - 1) / T, T>>>(p_emax, 0u, NN);
    fill_f<<<(NN + T - 1) / T, T>>>(p_den, 0.f, NN);
    fill_f<<<(NN * HID + T - 1) / T, T>>>(p_agg, 0.f, NN * HID);
    edge_pass1<<<edge_blocks, T>>>(edges);
    edge_pass2<<<edge_blocks, T>>>(edges);
    edge_pass3<<<edge_wblocks, T>>>(edges);
    bias_relu<<<(NN * HID + T - 1) / T, T>>>(b0);

    // ===== GAT layer 1 =====
    gemm_tile<<<dim3(gemm_gx, 2), T>>>(p_x1, HID, HID, NN, W1, HID, nullptr, p_h, HID, 0);
    attn_scores<<<node_wblocks, T>>>(as1, ad1);
    fill_u<<<(NN + T - 1) / T, T>>>(p_emax, 0u, NN);
    fill_f<<<(NN + T - 1) / T, T>>>(p_den, 0.f, NN);
    fill_f<<<(NN * HID + T - 1) / T, T>>>(p_agg, 0.f, NN * HID);
    edge_pass1<<<edge_blocks, T>>>(edges);
    edge_pass2<<<edge_blocks, T>>>(edges);
    edge_pass3<<<edge_wblocks, T>>>(edges);

    // 3) final node outputs + heads
    final_node<<<node_wblocks, T>>>(b1, Wa, ba, Wd, bd, out);

    // 4) edge predictions
    pred_kernel<<<(NE + T - 1) / T, T>>>(edges, pred);
}

// round 2
// speedup vs baseline: 1.8898x; 1.8898x over previous
#include <cuda_runtime.h>
#include <math.h>

#define NN   100000
#define NE   1600000
#define ET   (NE + NN)
#define VISD 512
#define TXTD 768
#define FEATD 131
#define LDA  132          // padded row stride for 131-wide features (528B, 16B-aligned)
#define HID  128
#define SCAN_B 1024
#define NBLK  ((NN + SCAN_B - 1) / SCAN_B)   // 98

// ---------------- scratch (device globals; no allocation allowed) ----------------
static __device__ float    g_node[NN * LDA];   // scattered + gelu'd node features
static __device__ float    g_h   [NN * HID];   // per-layer transformed features h = x @ W
static __device__ float    g_x1  [NN * HID];   // relu(layer0 output)
static __device__ float    g_agg [NN * HID];   // layer1 aggregation (raw)
static __device__ float    g_as  [NN];
static __device__ float    g_ad  [NN];
static __device__ float    g_ang [NN * 2];
static __device__ float    g_dis [NN * 2];
// CSR (by destination), includes self loops
static __device__ int      g_cnt [NN];
static __device__ int      g_rowptr[NN + 1];
static __device__ int      g_wofs[NN];
static __device__ int      g_csr [ET];
static __device__ int      g_bsum[128];

// ---------------- helpers ----------------
__device__ __forceinline__ float gelu_exact(float x) {
    return 0.5f * x * (1.0f + erff(x * 0.70710678118654752f));
}

__global__ void fill_f(float* p, float v, int n) {
    int i = blockIdx.x * blockDim.x + threadIdx.x;
    if (i < n) p[i] = v;
}
__global__ void fill_i(int* p, int v, int n) {
    int i = blockIdx.x * blockDim.x + threadIdx.x;
    if (i < n) p[i] = v;
}

// ---------------- CSR build ----------------
__global__ void hist_kernel(const int* __restrict__ edges) {
    int i = blockIdx.x * blockDim.x + threadIdx.x;
    if (i >= ET) return;
    int d = (i < NE) ? edges[2 * i + 1] : (i - NE);
    atomicAdd(&g_cnt[d], 1);
}

__global__ void scan_block() {
    __shared__ int sm[SCAN_B];
    int i = blockIdx.x * SCAN_B + threadIdx.x;
    int v = (i < NN) ? g_cnt[i] : 0;
    sm[threadIdx.x] = v;
    __syncthreads();
    #pragma unroll
    for (int o = 1; o < SCAN_B; o <<= 1) {
        int t = (threadIdx.x >= o) ? sm[threadIdx.x - o] : 0;
        __syncthreads();
        sm[threadIdx.x] += t;
        __syncthreads();
    }
    if (i < NN) g_rowptr[i] = sm[threadIdx.x] - v;     // exclusive within block
    if (threadIdx.x == SCAN_B - 1) g_bsum[blockIdx.x] = sm[SCAN_B - 1];
}

__global__ void scan_sums() {      // single block, 128 threads, NBLK<=128
    __shared__ int sm[128];
    int v = (threadIdx.x < NBLK) ? g_bsum[threadIdx.x] : 0;
    sm[threadIdx.x] = v;
    __syncthreads();
    #pragma unroll
    for (int o = 1; o < 128; o <<= 1) {
        int t = (threadIdx.x >= o) ? sm[threadIdx.x - o] : 0;
        __syncthreads();
        sm[threadIdx.x] += t;
        __syncthreads();
    }
    if (threadIdx.x < NBLK) g_bsum[threadIdx.x] = sm[threadIdx.x] - v;  // exclusive
}

__global__ void scan_add() {
    int i = blockIdx.x * blockDim.x + threadIdx.x;
    if (i < NN) {
        int v = g_rowptr[i] + g_bsum[i / SCAN_B];
        g_rowptr[i] = v;
        g_wofs[i]   = v;
    }
    if (i == 0) g_rowptr[NN] = ET;
}

__global__ void scatter_csr(const int* __restrict__ edges) {
    int i = blockIdx.x * blockDim.x + threadIdx.x;
    if (i >= ET) return;
    int s, d;
    if (i < NE) { s = edges[2 * i]; d = edges[2 * i + 1]; }
    else        { s = d = i - NE; }
    int pos = atomicAdd(&g_wofs[d], 1);
    g_csr[pos] = s;
}

// ---------------- generic tiled fp32 GEMM with optional row-scatter + gelu epilogue ----------------
__global__ void gemm_tile(const float* __restrict__ A, int lda, int K, int M,
                          const float* __restrict__ W, int wcols,
                          const float* __restrict__ bias,
                          float* __restrict__ C, int ldc, int ccol0,
                          const int* __restrict__ sidx, int do_gelu)
{
    __shared__ float As[16][64];
    __shared__ float Bs[16][64 + 4];
    const int row0 = blockIdx.x * 64;
    const int col0 = blockIdx.y * 64;
    const int t  = threadIdx.x;                // 256 threads
    const int tx = t & 15, ty = t >> 4;
    float acc[4][4] = {};

    for (int k0 = 0; k0 < K; k0 += 16) {
        {
            int r  = t >> 2;
            int kk = (t & 3) * 4;
            int gr = row0 + r;
            float4 v = make_float4(0.f, 0.f, 0.f, 0.f);
            if (gr < M) {
                if (k0 + kk + 3 < K) {
                    v = *reinterpret_cast<const float4*>(&A[(size_t)gr * lda + k0 + kk]);
                } else {
                    float tmp[4] = {0.f, 0.f, 0.f, 0.f};
                    #pragma unroll
                    for (int c = 0; c < 4; c++) {
                        int k = k0 + kk + c;
                        if (k < K) tmp[c] = A[(size_t)gr * lda + k];
                    }
                    v = make_float4(tmp[0], tmp[1], tmp[2], tmp[3]);
                }
            }
            As[kk + 0][r] = v.x; As[kk + 1][r] = v.y;
            As[kk + 2][r] = v.z; As[kk + 3][r] = v.w;
        }
        #pragma unroll
        for (int i = 0; i < 4; i++) {
            int idx = t + 256 * i;
            int kr = idx >> 6, c = idx & 63;
            int k = k0 + kr;
            Bs[kr][c] = (k < K) ? W[(size_t)k * wcols + col0 + c] : 0.f;
        }
        __syncthreads();
        #pragma unroll
        for (int k = 0; k < 16; k++) {
            float a[4], b[4];
            #pragma unroll
            for (int i = 0; i < 4; i++) a[i] = As[k][ty * 4 + i];
            #pragma unroll
            for (int j = 0; j < 4; j++) b[j] = Bs[k][tx * 4 + j];
            #pragma unroll
            for (int i = 0; i < 4; i++)
                #pragma unroll
                for (int j = 0; j < 4; j++)
                    acc[i][j] = fmaf(a[i], b[j], acc[i][j]);
        }
        __syncthreads();
    }
    #pragma unroll
    for (int i = 0; i < 4; i++) {
        int r = row0 + ty * 4 + i;
        if (r >= M) continue;
        int orow = sidx ? sidx[r] : r;
        #pragma unroll
        for (int j = 0; j < 4; j++) {
            int c = col0 + tx * 4 + j;
            float v = acc[i][j];
            if (bias) v += bias[c];
            if (do_gelu) v = gelu_exact(v);
            C[(size_t)orow * ldc + ccol0 + c] = v;
        }
    }
}

// ---------------- ars -> node cols 128..130 (scattered, gelu) ----------------
__global__ void ars_scatter(const float* __restrict__ ars, const int* __restrict__ ci) {
    int i = blockIdx.x * blockDim.x + threadIdx.x;
    if (i >= NN) return;
    int dst = ci[i];
    g_node[(size_t)dst * LDA + 128] = gelu_exact(ars[3 * i + 0]);
    g_node[(size_t)dst * LDA + 129] = gelu_exact(ars[3 * i + 1]);
    g_node[(size_t)dst * LDA + 130] = gelu_exact(ars[3 * i + 2]);
}

// ---------------- per-node attention scores ----------------
__global__ void attn_scores(const float* __restrict__ ws, const float* __restrict__ wd) {
    int gw   = (blockIdx.x * blockDim.x + threadIdx.x) >> 5;
    int lane = threadIdx.x & 31;
    if (gw >= NN) return;
    float4 hv = *reinterpret_cast<const float4*>(&g_h[(size_t)gw * HID + lane * 4]);
    float4 a  = *reinterpret_cast<const float4*>(&ws[lane * 4]);
    float4 b  = *reinterpret_cast<const float4*>(&wd[lane * 4]);
    float s = hv.x * a.x + hv.y * a.y + hv.z * a.z + hv.w * a.w;
    float d = hv.x * b.x + hv.y * b.y + hv.z * b.z + hv.w * b.w;
    #pragma unroll
    for (int o = 16; o; o >>= 1) {
        s += __shfl_xor_sync(0xffffffffu, s, o);
        d += __shfl_xor_sync(0xffffffffu, d, o);
    }
    if (lane == 0) { g_as[gw] = s; g_ad[gw] = d; }
}

// ---------------- pull-based GAT aggregation: warp per destination node ----------------
// out[w,:] = (optional relu)( sum_src alpha * h[src,:] + optional bias )
__global__ void gat_pull(const float* __restrict__ bias, int do_relu,
                         float* __restrict__ out)
{
    int w    = (blockIdx.x * blockDim.x + threadIdx.x) >> 5;
    int lane = threadIdx.x & 31;
    if (w >= NN) return;
    const int start = g_rowptr[w];
    const int end   = g_rowptr[w + 1];
    const float adw = g_ad[w];

    // online max + sum(exp) across this node's in-edges (lane-parallel)
    float m = -1e30f, ssum = 0.f;
    for (int i = start + lane; i < end; i += 32) {
        float e = g_as[g_csr[i]] + adw;
        e = (e > 0.f) ? e : 0.2f * e;
        if (e > m) { ssum = ssum * expf(m - e) + 1.0f; m = e; }
        else       { ssum += expf(e - m); }
    }
    #pragma unroll
    for (int o = 16; o; o >>= 1) {
        float mo = __shfl_xor_sync(0xffffffffu, m, o);
        float so = __shfl_xor_sync(0xffffffffu, ssum, o);
        float mn = fmaxf(m, mo);
        ssum = ssum * expf(m - mn) + so * expf(mo - mn);
        m = mn;
    }
    const float inv = 1.0f / (ssum + 1e-16f);

    // weighted feature gather: lane owns 4 contiguous features
    float4 acc = make_float4(0.f, 0.f, 0.f, 0.f);
    const float4* hb = reinterpret_cast<const float4*>(g_h);
    for (int i = start; i < end; i++) {
        int src = g_csr[i];                       // broadcast load
        float e = g_as[src] + adw;
        e = (e > 0.f) ? e : 0.2f * e;
        float alpha = expf(e - m) * inv;
        float4 hv = hb[(size_t)src * 32 + lane];
        acc.x = fmaf(alpha, hv.x, acc.x);
        acc.y = fmaf(alpha, hv.y, acc.y);
        acc.z = fmaf(alpha, hv.z, acc.z);
        acc.w = fmaf(alpha, hv.w, acc.w);
    }
    if (bias) {
        float4 bb = *reinterpret_cast<const float4*>(&bias[lane * 4]);
        acc.x += bb.x; acc.y += bb.y; acc.z += bb.z; acc.w += bb.w;
    }
    if (do_relu) {
        acc.x = fmaxf(acc.x, 0.f); acc.y = fmaxf(acc.y, 0.f);
        acc.z = fmaxf(acc.z, 0.f); acc.w = fmaxf(acc.w, 0.f);
    }
    *reinterpret_cast<float4*>(&out[(size_t)w * HID + lane * 4]) = acc;
}

// ---------------- final per-node: out = gelu(agg + b1); angles/dists heads ----------------
__global__ void final_node(const float* __restrict__ b1,
                           const float* __restrict__ Wa, const float* __restrict__ ba,
                           const float* __restrict__ Wd, const float* __restrict__ bd,
                           float* __restrict__ out)
{
    int gw   = (blockIdx.x * blockDim.x + threadIdx.x) >> 5;
    int lane = threadIdx.x & 31;
    if (gw >= NN) return;
    float4 g;
    {
        float4 v = *reinterpret_cast<const float4*>(&g_agg[(size_t)gw * HID + lane * 4]);
        float4 bb = *reinterpret_cast<const float4*>(&b1[lane * 4]);
        g.x = gelu_exact(v.x + bb.x);
        g.y = gelu_exact(v.y + bb.y);
        g.z = gelu_exact(v.z + bb.z);
        g.w = gelu_exact(v.w + bb.w);
    }
    *reinterpret_cast<float4*>(&out[(size_t)gw * HID + lane * 4]) = g;
    int k = lane * 4;
    float a0 = g.x * Wa[2 * k]     + g.y * Wa[2 * (k + 1)]     + g.z * Wa[2 * (k + 2)]     + g.w * Wa[2 * (k + 3)];
    float a1 = g.x * Wa[2 * k + 1] + g.y * Wa[2 * (k + 1) + 1] + g.z * Wa[2 * (k + 2) + 1] + g.w * Wa[2 * (k + 3) + 1];
    float d0 = g.x * Wd[2 * k]     + g.y * Wd[2 * (k + 1)]     + g.z * Wd[2 * (k + 2)]     + g.w * Wd[2 * (k + 3)];
    float d1 = g.x * Wd[2 * k + 1] + g.y * Wd[2 * (k + 1) + 1] + g.z * Wd[2 * (k + 2) + 1] + g.w * Wd[2 * (k + 3) + 1];
    #pragma unroll
    for (int o = 16; o; o >>= 1) {
        a0 += __shfl_xor_sync(0xffffffffu, a0, o);
        a1 += __shfl_xor_sync(0xffffffffu, a1, o);
        d0 += __shfl_xor_sync(0xffffffffu, d0, o);
        d1 += __shfl_xor_sync(0xffffffffu, d1, o);
    }
    if (lane == 0) {
        g_ang[2 * gw]     = a0 + ba[0];
        g_ang[2 * gw + 1] = a1 + ba[1];
        g_dis[2 * gw]     = d0 + bd[0];
        g_dis[2 * gw + 1] = d1 + bd[1];
    }
}

// ---------------- edge prediction ----------------
__global__ void pred_kernel(const int* __restrict__ edges, float* __restrict__ pred) {
    int i = blockIdx.x * blockDim.x + threadIdx.x;
    if (i >= NE) return;
    int s = edges[2 * i], d = edges[2 * i + 1];
    float ap = g_ang[2 * s] * g_ang[2 * d] + g_ang[2 * s + 1] * g_ang[2 * d + 1];
    float dp = g_dis[2 * s] * g_dis[2 * d] + g_dis[2 * s + 1] * g_dis[2 * d + 1];
    pred[2 * i]     = ap;
    pred[2 * i + 1] = dp;
}

// ---------------- launch ----------------
extern "C" void kernel_launch(void* const* d_in, const int* in_sizes, int n_in,
                              void* d_out, int out_size)
{
    const float* img  = (const float*)d_in[0];
    const float* txt  = (const float*)d_in[1];
    const int*   ci   = (const int*)  d_in[2];
    const int*   edges= (const int*)  d_in[4];
    const float* ars  = (const float*)d_in[5];
    const float* Wi   = (const float*)d_in[6];
    const float* bi   = (const float*)d_in[7];
    const float* Wt   = (const float*)d_in[8];
    const float* bt   = (const float*)d_in[9];
    const float* W0   = (const float*)d_in[10];
    const float* as0  = (const float*)d_in[11];
    const float* ad0  = (const float*)d_in[12];
    const float* b0   = (const float*)d_in[13];
    const float* W1   = (const float*)d_in[14];
    const float* as1  = (const float*)d_in[15];
    const float* ad1  = (const float*)d_in[16];
    const float* b1   = (const float*)d_in[17];
    const float* Wa   = (const float*)d_in[18];
    const float* ba   = (const float*)d_in[19];
    const float* Wd   = (const float*)d_in[20];
    const float* bd   = (const float*)d_in[21];
    float* out  = (float*)d_out;                       // [N,128]
    float* pred = (float*)d_out + (size_t)NN * HID;    // [E,2]

    float *p_node, *p_h, *p_x1, *p_agg;
    int *p_cnt;
    cudaGetSymbolAddress((void**)&p_node, g_node);
    cudaGetSymbolAddress((void**)&p_h,    g_h);
    cudaGetSymbolAddress((void**)&p_x1,   g_x1);
    cudaGetSymbolAddress((void**)&p_agg,  g_agg);
    cudaGetSymbolAddress((void**)&p_cnt,  g_cnt);

    const int T = 256;
    const int gemm_gx = (NN + 63) / 64;
    const int node_wblocks = ((NN * 32) + T - 1) / T;
    const int edge_blocks  = (ET + T - 1) / T;

    // ---- CSR build (independent of features) ----
    fill_i<<<(NN + T - 1) / T, T>>>(p_cnt, 0, NN);
    hist_kernel<<<edge_blocks, T>>>(edges);
    scan_block<<<NBLK, SCAN_B>>>();
    scan_sums<<<1, 128>>>();
    scan_add<<<(NN + T - 1) / T, T>>>();
    scatter_csr<<<edge_blocks, T>>>(edges);

    // ---- input projections, scattered directly into node with gelu ----
    fill_f<<<(NN * LDA + T - 1) / T, T>>>(p_node, 0.f, NN * LDA);
    gemm_tile<<<dim3(gemm_gx, 1), T>>>(img, VISD, VISD, NN, Wi, 64, bi, p_node, LDA, 0,  ci, 1);
    gemm_tile<<<dim3(gemm_gx, 1), T>>>(txt, TXTD, TXTD, NN, Wt, 64, bt, p_node, LDA, 64, ci, 1);
    ars_scatter<<<(NN + T - 1) / T, T>>>(ars, ci);

    // ===== GAT layer 0 =====
    gemm_tile<<<dim3(gemm_gx, 2), T>>>(p_node, LDA, FEATD, NN, W0, HID, nullptr, p_h, HID, 0, nullptr, 0);
    attn_scores<<<node_wblocks, T>>>(as0, ad0);
    gat_pull<<<node_wblocks, T>>>(b0, 1, p_x1);

    // ===== GAT layer 1 =====
    gemm_tile<<<dim3(gemm_gx, 2), T>>>(p_x1, HID, HID, NN, W1, HID, nullptr, p_h, HID, 0, nullptr, 0);
    attn_scores<<<node_wblocks, T>>>(as1, ad1);
    gat_pull<<<node_wblocks, T>>>(nullptr, 0, p_agg);

    // ---- final node outputs + heads ----
    final_node<<<node_wblocks, T>>>(b1, Wa, ba, Wd, bd, out);

    // ---- edge predictions ----
    pred_kernel<<<(NE + T - 1) / T, T>>>(edges, pred);
}